// round 15
// baseline (speedup 1.0000x reference)
#include <cuda_runtime.h>
#include <cuda_fp16.h>
#include <cstdint>
#include <cfloat>

// ---------------- problem constants ----------------
#define NB 16
#define NT 1024
#define NF 512
#define NG 2
#define NV 320
#define ND 128
#define NTOK (NB*NT)        // 16384
#define NJ (NG*NV)          // 640

// ---------------- device scratch (no cudaMalloc allowed) ----------------
__device__ __half g_xh[(size_t)NTOK * NF];       // fp16(x)
__device__ __half g_w0[(size_t)NJ * NF];         // fp16(w)
__device__ __half g_logits_h[(size_t)NTOK * NJ]; // 20 MB (fp16 logits)
__device__ float g_counts[NT * NG * NV];
__device__ float g_avg[NG * NV];

// ---------------- helpers ----------------
__device__ __forceinline__ uint32_t smem_u32(const void* p) {
    uint32_t a;
    asm("{ .reg .u64 t; cvta.to.shared.u64 t, %1; cvt.u32.u64 %0, t; }" : "=r"(a) : "l"(p));
    return a;
}
#define SW128(b) ((b) ^ (((b) >> 3) & 0x70))
#define CP_ASYNC16(s, g) \
    asm volatile("cp.async.cg.shared.global [%0], [%1], 16;" :: "r"(s), "l"(g))
#define CP_COMMIT() asm volatile("cp.async.commit_group;" ::: "memory")
#define CP_WAIT(n)  asm volatile("cp.async.wait_group %0;" :: "n"(n) : "memory")
#define LDSM_X4(r0, r1, r2, r3, addr) \
    asm volatile("ldmatrix.sync.aligned.m8n8.x4.shared.b16 {%0,%1,%2,%3}, [%4];" \
        : "=r"(r0), "=r"(r1), "=r"(r2), "=r"(r3) : "r"(addr))
#define MMA16816(c, a0, a1, a2, a3, b0, b1) \
    asm volatile("mma.sync.aligned.m16n8k16.row.col.f32.f16.f16.f32 " \
        "{%0,%1,%2,%3}, {%4,%5,%6,%7}, {%8,%9}, {%0,%1,%2,%3};" \
        : "+f"((c)[0]), "+f"((c)[1]), "+f"((c)[2]), "+f"((c)[3]) \
        : "r"(a0), "r"(a1), "r"(a2), "r"(a3), "r"(b0), "r"(b1))

// exact fp32 dot over 512 features, warp-collective; result valid on all lanes
__device__ __forceinline__ float warp_dot512(const float* __restrict__ a,
                                             const float* __restrict__ b, int lane) {
    const float4* a4 = (const float4*)a;
    const float4* b4 = (const float4*)b;
    float s = 0.f;
    #pragma unroll
    for (int u = 0; u < 4; u++) {
        float4 av = a4[lane + u * 32], bv = b4[lane + u * 32];
        s += av.x * bv.x + av.y * bv.y + av.z * bv.z + av.w * bv.w;
    }
    #pragma unroll
    for (int o = 16; o; o >>= 1) s += __shfl_xor_sync(0xffffffffu, s, o);
    return s;
}

// ---------------- split + zero (merged), 4 float4 per thread ----------------
#define X4 (NTOK * NF / 4)   // 2097152
#define W4 (NJ * NF / 4)     // 81920
__global__ __launch_bounds__(256) void split_zero_kernel(
    const float4* __restrict__ xs, const float4* __restrict__ ws,
    float* __restrict__ out_scalars)
{
    int i0 = blockIdx.x * 1024 + threadIdx.x;
    #pragma unroll
    for (int k = 0; k < 4; k++) {
        int i = i0 + k * 256;
        if (i < NT * NG * NV) g_counts[i] = 0.f;
        if (i < NG * NV) g_avg[i] = 0.f;
        if (i < 2) out_scalars[i] = 0.f;

        if (i < X4) {
            float4 v = xs[i];
            __half2* d0 = (__half2*)g_xh;
            d0[2*i]   = __halves2half2(__float2half_rn(v.x), __float2half_rn(v.y));
            d0[2*i+1] = __halves2half2(__float2half_rn(v.z), __float2half_rn(v.w));
        } else if (i < X4 + W4) {
            int idx = i - X4;
            float4 v = ws[idx];
            __half2* d0 = (__half2*)g_w0;
            d0[2*idx]   = __halves2half2(__float2half_rn(v.x), __float2half_rn(v.y));
            d0[2*idx+1] = __halves2half2(__float2half_rn(v.z), __float2half_rn(v.w));
        }
    }
}

// ---------------- HMMA GEMM: BM=128 BN=128, 4 warps, warp tile 64x64 ----------------
// LDSM/MMA = 0.25. 3-stage cp.async pipeline, SW128, 2 CTAs/SM, 640 CTAs.
#define STAGES 3
#define STG_A 16384                 // 128 rows x 128B
#define STG_B 16384                 // 128 rows x 128B
#define STG_BYTES (STG_A + STG_B)   // 32768
#define GEMM_SMEM (STAGES * STG_BYTES)   // 98304

__global__ __launch_bounds__(128, 2) void gemm_mma_kernel(const float* __restrict__ bias)
{
    extern __shared__ __align__(1024) char smem[];
    const uint32_t sb = smem_u32(smem);
    const int tid = threadIdx.x, lane = tid & 31, wid = tid >> 5;
    const int wm = (wid & 1) * 64;       // warp m offset
    const int wn = (wid >> 1) * 64;      // warp n offset
    const int m0 = blockIdx.y * 128;
    const int j0 = blockIdx.x * 128;

    float acc[4][8][4];                  // 128 regs
    #pragma unroll
    for (int mt = 0; mt < 4; mt++)
        #pragma unroll
        for (int nt = 0; nt < 8; nt++)
            #pragma unroll
            for (int c = 0; c < 4; c++) acc[mt][nt][c] = 0.f;

    auto load_stage = [&](int s, int it) {
        const int kk = it * 64;
        const uint32_t stA = sb + s * STG_BYTES;
        const uint32_t stB = stA + STG_A;
        #pragma unroll
        for (int n = 0; n < 8; n++) {
            int i = tid + n * 128;
            int r = i >> 3, u = i & 7;
            CP_ASYNC16(stA + SW128(r * 128 + u * 16),
                       (const void*)(g_xh + (size_t)(m0 + r) * NF + kk + u * 8));
        }
        #pragma unroll
        for (int n = 0; n < 8; n++) {
            int i = tid + n * 128;
            int r = i >> 3, u = i & 7;
            CP_ASYNC16(stB + SW128(r * 128 + u * 16),
                       (const void*)(g_w0 + (size_t)(j0 + r) * NF + kk + u * 8));
        }
        CP_COMMIT();
    };

    load_stage(0, 0);
    load_stage(1, 1);

    for (int it = 0; it < 8; it++) {
        CP_WAIT(1);
        __syncthreads();
        const int s = it % STAGES;
        const uint32_t stA = sb + s * STG_BYTES;
        const uint32_t stB = stA + STG_A;
        #pragma unroll
        for (int ks = 0; ks < 4; ks++) {
            uint32_t a[4][4], b[4][4];
            #pragma unroll
            for (int mt = 0; mt < 4; mt++) {
                uint32_t off = (uint32_t)(wm + mt * 16 + (lane & 15)) * 128 + ks * 32 + (lane >> 4) * 16;
                LDSM_X4(a[mt][0], a[mt][1], a[mt][2], a[mt][3], stA + SW128(off));
            }
            #pragma unroll
            for (int nb = 0; nb < 4; nb++) {
                uint32_t off = (uint32_t)(wn + nb * 16 + (lane & 15)) * 128 + ks * 32 + (lane >> 4) * 16;
                LDSM_X4(b[nb][0], b[nb][1], b[nb][2], b[nb][3], stB + SW128(off));
            }
            #pragma unroll
            for (int mt = 0; mt < 4; mt++)
                #pragma unroll
                for (int nt = 0; nt < 8; nt++)
                    MMA16816(acc[mt][nt], a[mt][0], a[mt][1], a[mt][2], a[mt][3],
                             b[nt >> 1][nt & 1], b[nt >> 1][(nt & 1) + 2]);
        }
        __syncthreads();
        if (it + 2 < 8) load_stage((it + 2) % STAGES, it + 2);
    }

    // ---- store: add bias, convert to fp16, write ----
    #pragma unroll
    for (int mt = 0; mt < 4; mt++) {
        #pragma unroll
        for (int nt = 0; nt < 8; nt++) {
            int row = m0 + wm + mt * 16 + (lane >> 2);
            int col = j0 + wn + nt * 8 + (lane & 3) * 2;
            float2 bv = *(const float2*)(bias + col);
            __half2 h0 = __halves2half2(__float2half_rn(acc[mt][nt][0] + bv.x),
                                        __float2half_rn(acc[mt][nt][1] + bv.y));
            __half2 h1 = __halves2half2(__float2half_rn(acc[mt][nt][2] + bv.x),
                                        __float2half_rn(acc[mt][nt][3] + bv.y));
            *(__half2*)(g_logits_h + (size_t)row * NJ + col) = h0;
            *(__half2*)(g_logits_h + (size_t)(row + 8) * NJ + col) = h1;
        }
    }
}

// ---------------- epilogue (R14, proven): redux-key argmax + lean test ----------------
#define DELTA 0.125f
#define BUFB 1920
__global__ __launch_bounds__(256, 5) void epilogue_kernel(
    const float* __restrict__ x, const float* __restrict__ w_proj,
    const float* __restrict__ bias,
    const float* __restrict__ gumbel, const float* __restrict__ codebook,
    float* __restrict__ out)
{
    __shared__ float sAvg[8][NV];                    // 10240 B
    __shared__ __align__(16) char pbuf[8][2][BUFB];  // 30720 B

    const int tid = threadIdx.x;
    const int wid = tid >> 5;
    const int lane = tid & 31;
    const int g = wid & 1;

    for (int i = lane; i < NV; i += 32) sAvg[wid][i] = 0.f;

    auto prefetch = [&](int slot, int task) {
        int n = task >> 1;
        uint32_t dst = smem_u32(&pbuf[wid][slot][0]);
        const char* lsrc = (const char*)(g_logits_h + (size_t)n * NJ + g * NV);
        const char* gsrc = (const char*)(gumbel + (size_t)n * NJ + g * NV);
        #pragma unroll
        for (int c = lane; c < 120; c += 32) {
            if (c < 40) CP_ASYNC16(dst + c * 16, lsrc + c * 16);
            else        CP_ASYNC16(dst + 640 + (c - 40) * 16, gsrc + (size_t)(c - 40) * 16);
        }
        CP_COMMIT();
    };

    const int t0 = blockIdx.x * 32 + wid;
    prefetch(0, t0);
    prefetch(1, t0 + 8);

    for (int it = 0; it < 4; it++) {
        const int task = t0 + it * 8;
        const int slot = it & 1;
        if (it < 3) { CP_WAIT(1); } else { CP_WAIT(0); }
        __syncwarp();

        const int n = task >> 1;
        const __half2* lrow2 = (const __half2*)&pbuf[wid][slot][0];
        const float* grow = (const float*)&pbuf[wid][slot][640];
        const float2* grow2 = (const float2*)grow;

        float l[10];
        float bestL = -FLT_MAX; int k1 = 0;
        float bestG = -FLT_MAX; int k2 = 0;
        #pragma unroll
        for (int i = 0; i < 5; i++) {
            int p = lane + i * 32;
            float2 lv = __half22float2(lrow2[p]);
            float2 gv = grow2[p];
            l[2*i]   = lv.x;
            l[2*i+1] = lv.y;
            int v0 = p * 2;
            if (lv.x > bestL) { bestL = lv.x; k1 = v0; }
            if (lv.y > bestL) { bestL = lv.y; k1 = v0 + 1; }
            float g0 = lv.x + gv.x, g1 = lv.y + gv.y;
            if (g0 > bestG) { bestG = g0; k2 = v0; }
            if (g1 > bestG) { bestG = g1; k2 = v0 + 1; }
        }

        {
            unsigned hb = __half_as_ushort(__float2half_rn(bestL));
            unsigned mL = hb ^ ((hb & 0x8000u) ? 0xFFFFu : 0x8000u);
            unsigned keyL = (mL << 16) | (unsigned)(1023 - k1);
            keyL = __reduce_max_sync(0xffffffffu, keyL);
            k1 = 1023 - (int)(keyL & 0xFFFFu);
            unsigned m = keyL >> 16;
            unsigned short b = (m & 0x8000u) ? (unsigned short)(m ^ 0x8000u)
                                             : (unsigned short)(m ^ 0xFFFFu);
            bestL = __half2float(__ushort_as_half(b));
        }
        {
            unsigned ug = __float_as_uint(bestG);
            unsigned mG = ug ^ ((unsigned)((int)ug >> 31) | 0x80000000u);
            unsigned keyG = (mG & 0xFFFFFC00u) | (unsigned)(1023 - k2);
            keyG = __reduce_max_sync(0xffffffffu, keyG);
            k2 = 1023 - (int)(keyG & 0x3FFu);
            unsigned m = (keyG & 0xFFFFFC00u) | 0x200u;
            unsigned b = (m & 0x80000000u) ? (m ^ 0x80000000u) : ~m;
            bestG = __uint_as_float(b);
        }

        const float thL = bestL - DELTA;
        const float thG = bestG - DELTA - 0.01f;
        int cl = 0, cg = 0;
        #pragma unroll
        for (int i = 0; i < 5; i++) {
            float2 gv = grow2[lane + i * 32];
            cl += (l[2*i] > thL) + (l[2*i+1] > thL);
            cg += (l[2*i] + gv.x > thG) + (l[2*i+1] + gv.y > thG);
        }
        unsigned bl1 = __ballot_sync(0xffffffffu, cl > 0);
        unsigned bl2 = __ballot_sync(0xffffffffu, cl > 1);
        unsigned bg1 = __ballot_sync(0xffffffffu, cg > 0);
        unsigned bg2 = __ballot_sync(0xffffffffu, cg > 1);

        if (__popc(bl1) > 1 || bl2) {
            const float* xr = x + (size_t)n * NF;
            float be = -FLT_MAX; int bi = 0;
            #pragma unroll 1
            for (int i = 0; i < 5; i++) {
                #pragma unroll
                for (int slot2 = 0; slot2 < 2; slot2++) {
                    unsigned m = __ballot_sync(0xffffffffu, l[2*i+slot2] > thL);
                    while (m) {
                        int src = __ffs(m) - 1; m &= m - 1;
                        int v = (src + i * 32) * 2 + slot2;
                        float e = warp_dot512(xr, w_proj + (size_t)(g * NV + v) * NF, lane)
                                  + bias[g * NV + v];
                        if (e > be || (e == be && v < bi)) { be = e; bi = v; }
                    }
                }
            }
            k1 = bi;
        }
        if (__popc(bg1) > 1 || bg2) {
            const float* xr = x + (size_t)n * NF;
            float be = -FLT_MAX; int bi = 0;
            #pragma unroll 1
            for (int i = 0; i < 5; i++) {
                #pragma unroll
                for (int slot2 = 0; slot2 < 2; slot2++) {
                    float2 gv = grow2[lane + i * 32];
                    float lg = l[2*i+slot2] + (slot2 ? gv.y : gv.x);
                    unsigned m = __ballot_sync(0xffffffffu, lg > thG);
                    while (m) {
                        int src = __ffs(m) - 1; m &= m - 1;
                        int v = (src + i * 32) * 2 + slot2;
                        float e = warp_dot512(xr, w_proj + (size_t)(g * NV + v) * NF, lane)
                                  + bias[g * NV + v] + grow[v];
                        if (e > be || (e == be && v < bi)) { be = e; bi = v; }
                    }
                }
            }
            k2 = bi;
        }

        float s = 0.f;
        #pragma unroll
        for (int i = 0; i < 10; i++) { l[i] = __expf(l[i] - bestL); s += l[i]; }
        #pragma unroll
        for (int off = 16; off; off >>= 1) s += __shfl_xor_sync(0xffffffffu, s, off);
        float inv = 1.0f / s;
        #pragma unroll
        for (int i = 0; i < 5; i++) {
            int v0 = (lane + i * 32) * 2;
            sAvg[wid][v0]     += l[2*i]   * inv;
            sAvg[wid][v0 + 1] += l[2*i+1] * inv;
        }

        if (lane == 0)
            atomicAdd(&g_counts[((n & (NT - 1)) * NG + g) * NV + k1], 1.0f);

        float4 cb = ((const float4*)(codebook + (size_t)(g * NV + k2) * ND))[lane];
        ((float4*)(out + (size_t)n * (NG * ND) + g * ND))[lane] = cb;

        __syncwarp();
        if (it + 2 < 4) prefetch(slot, task + 16);
    }

    __syncthreads();
    for (int xx = tid; xx < NG * NV; xx += 256) {
        int gg = xx / NV, v = xx - gg * NV;
        float s = sAvg[gg][v] + sAvg[gg + 2][v] + sAvg[gg + 4][v] + sAvg[gg + 6][v];
        atomicAdd(&g_avg[xx], s);
    }
}

// ---------------- perplexity reduction: warp-per-row, float4 loads ----------------
__global__ __launch_bounds__(256) void perp_kernel(float* __restrict__ out) {
    const int row = blockIdx.x * 8 + (threadIdx.x >> 5);
    const int lane = threadIdx.x & 31;
    if (row >= NT * NG + NG) return;
    const float* vals;
    float scale;
    int slot;
    if (row < NT * NG) { vals = g_counts + (size_t)row * NV; scale = 1.0f / NB; slot = 0; }
    else { vals = g_avg + (size_t)(row - NT * NG) * NV; scale = 1.0f / (float)NTOK; slot = 1; }
    const float4* v4 = (const float4*)vals;
    float t = 0.f;
    #pragma unroll
    for (int i = 0; i < 2; i++) {
        float4 q = v4[lane + i * 32];
        float p0 = q.x * scale, p1 = q.y * scale, p2 = q.z * scale, p3 = q.w * scale;
        t += p0 * __logf(p0 + 1e-7f) + p1 * __logf(p1 + 1e-7f)
           + p2 * __logf(p2 + 1e-7f) + p3 * __logf(p3 + 1e-7f);
    }
    if (lane < 16) {
        float4 q = v4[lane + 64];
        float p0 = q.x * scale, p1 = q.y * scale, p2 = q.z * scale, p3 = q.w * scale;
        t += p0 * __logf(p0 + 1e-7f) + p1 * __logf(p1 + 1e-7f)
           + p2 * __logf(p2 + 1e-7f) + p3 * __logf(p3 + 1e-7f);
    }
    #pragma unroll
    for (int off = 16; off; off >>= 1) t += __shfl_xor_sync(0xffffffffu, t, off);
    if (lane == 0) atomicAdd(out + slot, __expf(-t));
}

// ---------------- launch ----------------
extern "C" void kernel_launch(void* const* d_in, const int* in_sizes, int n_in,
                              void* d_out, int out_size)
{
    const float* x        = (const float*)d_in[0];  // (16,1024,512)
    const float* w_proj   = (const float*)d_in[1];  // (640,512)
    const float* b_proj   = (const float*)d_in[2];  // (640)
    const float* codebook = (const float*)d_in[3];  // (1,640,128)
    const float* gumbel   = (const float*)d_in[4];  // (16384,2,320)
    float* out = (float*)d_out;
    float* scalars = out + (out_size - 2);

    cudaFuncSetAttribute(gemm_mma_kernel, cudaFuncAttributeMaxDynamicSharedMemorySize, GEMM_SMEM);

    split_zero_kernel<<<(X4 + W4 + 1023) / 1024, 256>>>(
        (const float4*)x, (const float4*)w_proj, scalars);

    dim3 ggrid(NJ / 128, NTOK / 128);   // (5, 128) = 640 CTAs
    gemm_mma_kernel<<<ggrid, 128, GEMM_SMEM>>>(b_proj);

    epilogue_kernel<<<1024, 256>>>(x, w_proj, b_proj, gumbel, codebook, out);

    perp_kernel<<<(NT * NG + NG + 7) / 8, 256>>>(scalars);
}

// round 16
// speedup vs baseline: 1.0495x; 1.0495x over previous
#include <cuda_runtime.h>
#include <cuda_fp16.h>
#include <cstdint>
#include <cfloat>

// ---------------- problem constants ----------------
#define NB 16
#define NT 1024
#define NF 512
#define NG 2
#define NV 320
#define ND 128
#define NTOK (NB*NT)        // 16384
#define NJ (NG*NV)          // 640

// ---------------- device scratch (no cudaMalloc allowed) ----------------
__device__ __half g_xh[(size_t)NTOK * NF];       // fp16(x)
__device__ __half g_w0[(size_t)NJ * NF];         // fp16(w)
__device__ __half g_logits_h[(size_t)NTOK * NJ]; // 20 MB (fp16 logits)
__device__ unsigned short g_k1[NT * NG * NB];    // argmax table: [(t,g),b]
__device__ float g_avg[NG * NV];

// ---------------- helpers ----------------
__device__ __forceinline__ uint32_t smem_u32(const void* p) {
    uint32_t a;
    asm("{ .reg .u64 t; cvta.to.shared.u64 t, %1; cvt.u32.u64 %0, t; }" : "=r"(a) : "l"(p));
    return a;
}
#define SW128(b) ((b) ^ (((b) >> 3) & 0x70))
#define CP_ASYNC16(s, g) \
    asm volatile("cp.async.cg.shared.global [%0], [%1], 16;" :: "r"(s), "l"(g))
#define CP_COMMIT() asm volatile("cp.async.commit_group;" ::: "memory")
#define CP_WAIT(n)  asm volatile("cp.async.wait_group %0;" :: "n"(n) : "memory")
#define LDSM_X4(r0, r1, r2, r3, addr) \
    asm volatile("ldmatrix.sync.aligned.m8n8.x4.shared.b16 {%0,%1,%2,%3}, [%4];" \
        : "=r"(r0), "=r"(r1), "=r"(r2), "=r"(r3) : "r"(addr))
#define MMA16816(c, a0, a1, a2, a3, b0, b1) \
    asm volatile("mma.sync.aligned.m16n8k16.row.col.f32.f16.f16.f32 " \
        "{%0,%1,%2,%3}, {%4,%5,%6,%7}, {%8,%9}, {%0,%1,%2,%3};" \
        : "+f"((c)[0]), "+f"((c)[1]), "+f"((c)[2]), "+f"((c)[3]) \
        : "r"(a0), "r"(a1), "r"(a2), "r"(a3), "r"(b0), "r"(b1))

// exact fp32 dot over 512 features, warp-collective; result valid on all lanes
__device__ __forceinline__ float warp_dot512(const float* __restrict__ a,
                                             const float* __restrict__ b, int lane) {
    const float4* a4 = (const float4*)a;
    const float4* b4 = (const float4*)b;
    float s = 0.f;
    #pragma unroll
    for (int u = 0; u < 4; u++) {
        float4 av = a4[lane + u * 32], bv = b4[lane + u * 32];
        s += av.x * bv.x + av.y * bv.y + av.z * bv.z + av.w * bv.w;
    }
    #pragma unroll
    for (int o = 16; o; o >>= 1) s += __shfl_xor_sync(0xffffffffu, s, o);
    return s;
}

// ---------------- split + zero (merged), 4 float4 per thread ----------------
#define X4 (NTOK * NF / 4)   // 2097152
#define W4 (NJ * NF / 4)     // 81920
__global__ __launch_bounds__(256) void split_zero_kernel(
    const float4* __restrict__ xs, const float4* __restrict__ ws,
    float* __restrict__ out_scalars)
{
    int i0 = blockIdx.x * 1024 + threadIdx.x;
    #pragma unroll
    for (int k = 0; k < 4; k++) {
        int i = i0 + k * 256;
        if (i < NG * NV) g_avg[i] = 0.f;
        if (i < 2) out_scalars[i] = 0.f;

        if (i < X4) {
            float4 v = xs[i];
            __half2* d0 = (__half2*)g_xh;
            d0[2*i]   = __halves2half2(__float2half_rn(v.x), __float2half_rn(v.y));
            d0[2*i+1] = __halves2half2(__float2half_rn(v.z), __float2half_rn(v.w));
        } else if (i < X4 + W4) {
            int idx = i - X4;
            float4 v = ws[idx];
            __half2* d0 = (__half2*)g_w0;
            d0[2*idx]   = __halves2half2(__float2half_rn(v.x), __float2half_rn(v.y));
            d0[2*idx+1] = __halves2half2(__float2half_rn(v.z), __float2half_rn(v.w));
        }
    }
}

// ---------------- HMMA GEMM: single fp16 pass (R13 geometry, proven) ----------------
#define STAGES 3
#define STG_A 16384                 // 128 rows x 128B
#define STG_B 8192                  // 64 rows x 128B
#define STG_BYTES (STG_A + STG_B)   // 24576
#define GEMM_SMEM (STAGES * STG_BYTES)   // 73728

__global__ __launch_bounds__(128, 3) void gemm_mma_kernel(const float* __restrict__ bias)
{
    extern __shared__ __align__(1024) char smem[];
    const uint32_t sb = smem_u32(smem);
    const int tid = threadIdx.x, lane = tid & 31, wid = tid >> 5;
    const int wm = (wid & 1) * 64;
    const int wn = (wid >> 1) * 32;
    const int m0 = blockIdx.y * 128;
    const int j0 = blockIdx.x * 64;

    float acc[4][4][4];
    #pragma unroll
    for (int mt = 0; mt < 4; mt++)
        #pragma unroll
        for (int nt = 0; nt < 4; nt++)
            #pragma unroll
            for (int c = 0; c < 4; c++) acc[mt][nt][c] = 0.f;

    auto load_stage = [&](int s, int it) {
        const int kk = it * 64;
        const uint32_t stA = sb + s * STG_BYTES;
        const uint32_t stB = stA + STG_A;
        #pragma unroll
        for (int n = 0; n < 8; n++) {
            int i = tid + n * 128;
            int r = i >> 3, u = i & 7;
            CP_ASYNC16(stA + SW128(r * 128 + u * 16),
                       (const void*)(g_xh + (size_t)(m0 + r) * NF + kk + u * 8));
        }
        #pragma unroll
        for (int n = 0; n < 4; n++) {
            int i = tid + n * 128;
            int r = i >> 3, u = i & 7;
            CP_ASYNC16(stB + SW128(r * 128 + u * 16),
                       (const void*)(g_w0 + (size_t)(j0 + r) * NF + kk + u * 8));
        }
        CP_COMMIT();
    };

    load_stage(0, 0);
    load_stage(1, 1);

    for (int it = 0; it < 8; it++) {
        CP_WAIT(1);
        __syncthreads();
        const int s = it % STAGES;
        const uint32_t stA = sb + s * STG_BYTES;
        const uint32_t stB = stA + STG_A;
        #pragma unroll
        for (int ks = 0; ks < 4; ks++) {
            uint32_t a[4][4], b[2][4];
            #pragma unroll
            for (int mt = 0; mt < 4; mt++) {
                uint32_t off = (uint32_t)(wm + mt * 16 + (lane & 15)) * 128 + ks * 32 + (lane >> 4) * 16;
                LDSM_X4(a[mt][0], a[mt][1], a[mt][2], a[mt][3], stA + SW128(off));
            }
            #pragma unroll
            for (int nb = 0; nb < 2; nb++) {
                uint32_t off = (uint32_t)(wn + nb * 16 + (lane & 15)) * 128 + ks * 32 + (lane >> 4) * 16;
                LDSM_X4(b[nb][0], b[nb][1], b[nb][2], b[nb][3], stB + SW128(off));
            }
            #pragma unroll
            for (int mt = 0; mt < 4; mt++)
                #pragma unroll
                for (int nt = 0; nt < 4; nt++)
                    MMA16816(acc[mt][nt], a[mt][0], a[mt][1], a[mt][2], a[mt][3],
                             b[nt >> 1][nt & 1], b[nt >> 1][(nt & 1) + 2]);
        }
        __syncthreads();
        if (it + 2 < 8) load_stage((it + 2) % STAGES, it + 2);
    }

    #pragma unroll
    for (int mt = 0; mt < 4; mt++) {
        #pragma unroll
        for (int nt = 0; nt < 4; nt++) {
            int row = m0 + wm + mt * 16 + (lane >> 2);
            int col = j0 + wn + nt * 8 + (lane & 3) * 2;
            float2 bv = *(const float2*)(bias + col);
            __half2 h0 = __halves2half2(__float2half_rn(acc[mt][nt][0] + bv.x),
                                        __float2half_rn(acc[mt][nt][1] + bv.y));
            __half2 h1 = __halves2half2(__float2half_rn(acc[mt][nt][2] + bv.x),
                                        __float2half_rn(acc[mt][nt][3] + bv.y));
            *(__half2*)(g_logits_h + (size_t)row * NJ + col) = h0;
            *(__half2*)(g_logits_h + (size_t)(row + 8) * NJ + col) = h1;
        }
    }
}

// ---------------- epilogue (R14 proven, atomic -> uint16 store) ----------------
#define DELTA 0.125f
#define BUFB 1920
__global__ __launch_bounds__(256, 5) void epilogue_kernel(
    const float* __restrict__ x, const float* __restrict__ w_proj,
    const float* __restrict__ bias,
    const float* __restrict__ gumbel, const float* __restrict__ codebook,
    float* __restrict__ out)
{
    __shared__ float sAvg[8][NV];                    // 10240 B
    __shared__ __align__(16) char pbuf[8][2][BUFB];  // 30720 B

    const int tid = threadIdx.x;
    const int wid = tid >> 5;
    const int lane = tid & 31;
    const int g = wid & 1;

    for (int i = lane; i < NV; i += 32) sAvg[wid][i] = 0.f;

    auto prefetch = [&](int slot, int task) {
        int n = task >> 1;
        uint32_t dst = smem_u32(&pbuf[wid][slot][0]);
        const char* lsrc = (const char*)(g_logits_h + (size_t)n * NJ + g * NV);
        const char* gsrc = (const char*)(gumbel + (size_t)n * NJ + g * NV);
        #pragma unroll
        for (int c = lane; c < 120; c += 32) {
            if (c < 40) CP_ASYNC16(dst + c * 16, lsrc + c * 16);
            else        CP_ASYNC16(dst + 640 + (c - 40) * 16, gsrc + (size_t)(c - 40) * 16);
        }
        CP_COMMIT();
    };

    const int t0 = blockIdx.x * 32 + wid;
    prefetch(0, t0);
    prefetch(1, t0 + 8);

    for (int it = 0; it < 4; it++) {
        const int task = t0 + it * 8;
        const int slot = it & 1;
        if (it < 3) { CP_WAIT(1); } else { CP_WAIT(0); }
        __syncwarp();

        const int n = task >> 1;
        const __half2* lrow2 = (const __half2*)&pbuf[wid][slot][0];
        const float* grow = (const float*)&pbuf[wid][slot][640];
        const float2* grow2 = (const float2*)grow;

        float l[10];
        float bestL = -FLT_MAX; int k1 = 0;
        float bestG = -FLT_MAX; int k2 = 0;
        #pragma unroll
        for (int i = 0; i < 5; i++) {
            int p = lane + i * 32;
            float2 lv = __half22float2(lrow2[p]);
            float2 gv = grow2[p];
            l[2*i]   = lv.x;
            l[2*i+1] = lv.y;
            int v0 = p * 2;
            if (lv.x > bestL) { bestL = lv.x; k1 = v0; }
            if (lv.y > bestL) { bestL = lv.y; k1 = v0 + 1; }
            float g0 = lv.x + gv.x, g1 = lv.y + gv.y;
            if (g0 > bestG) { bestG = g0; k2 = v0; }
            if (g1 > bestG) { bestG = g1; k2 = v0 + 1; }
        }

        {
            unsigned hb = __half_as_ushort(__float2half_rn(bestL));
            unsigned mL = hb ^ ((hb & 0x8000u) ? 0xFFFFu : 0x8000u);
            unsigned keyL = (mL << 16) | (unsigned)(1023 - k1);
            keyL = __reduce_max_sync(0xffffffffu, keyL);
            k1 = 1023 - (int)(keyL & 0xFFFFu);
            unsigned m = keyL >> 16;
            unsigned short b = (m & 0x8000u) ? (unsigned short)(m ^ 0x8000u)
                                             : (unsigned short)(m ^ 0xFFFFu);
            bestL = __half2float(__ushort_as_half(b));
        }
        {
            unsigned ug = __float_as_uint(bestG);
            unsigned mG = ug ^ ((unsigned)((int)ug >> 31) | 0x80000000u);
            unsigned keyG = (mG & 0xFFFFFC00u) | (unsigned)(1023 - k2);
            keyG = __reduce_max_sync(0xffffffffu, keyG);
            k2 = 1023 - (int)(keyG & 0x3FFu);
            unsigned m = (keyG & 0xFFFFFC00u) | 0x200u;
            unsigned b = (m & 0x80000000u) ? (m ^ 0x80000000u) : ~m;
            bestG = __uint_as_float(b);
        }

        const float thL = bestL - DELTA;
        const float thG = bestG - DELTA - 0.01f;
        int cl = 0, cg = 0;
        #pragma unroll
        for (int i = 0; i < 5; i++) {
            float2 gv = grow2[lane + i * 32];
            cl += (l[2*i] > thL) + (l[2*i+1] > thL);
            cg += (l[2*i] + gv.x > thG) + (l[2*i+1] + gv.y > thG);
        }
        unsigned bl1 = __ballot_sync(0xffffffffu, cl > 0);
        unsigned bl2 = __ballot_sync(0xffffffffu, cl > 1);
        unsigned bg1 = __ballot_sync(0xffffffffu, cg > 0);
        unsigned bg2 = __ballot_sync(0xffffffffu, cg > 1);

        if (__popc(bl1) > 1 || bl2) {
            const float* xr = x + (size_t)n * NF;
            float be = -FLT_MAX; int bi = 0;
            #pragma unroll 1
            for (int i = 0; i < 5; i++) {
                #pragma unroll
                for (int slot2 = 0; slot2 < 2; slot2++) {
                    unsigned m = __ballot_sync(0xffffffffu, l[2*i+slot2] > thL);
                    while (m) {
                        int src = __ffs(m) - 1; m &= m - 1;
                        int v = (src + i * 32) * 2 + slot2;
                        float e = warp_dot512(xr, w_proj + (size_t)(g * NV + v) * NF, lane)
                                  + bias[g * NV + v];
                        if (e > be || (e == be && v < bi)) { be = e; bi = v; }
                    }
                }
            }
            k1 = bi;
        }
        if (__popc(bg1) > 1 || bg2) {
            const float* xr = x + (size_t)n * NF;
            float be = -FLT_MAX; int bi = 0;
            #pragma unroll 1
            for (int i = 0; i < 5; i++) {
                #pragma unroll
                for (int slot2 = 0; slot2 < 2; slot2++) {
                    float2 gv = grow2[lane + i * 32];
                    float lg = l[2*i+slot2] + (slot2 ? gv.y : gv.x);
                    unsigned m = __ballot_sync(0xffffffffu, lg > thG);
                    while (m) {
                        int src = __ffs(m) - 1; m &= m - 1;
                        int v = (src + i * 32) * 2 + slot2;
                        float e = warp_dot512(xr, w_proj + (size_t)(g * NV + v) * NF, lane)
                                  + bias[g * NV + v] + grow[v];
                        if (e > be || (e == be && v < bi)) { be = e; bi = v; }
                    }
                }
            }
            k2 = bi;
        }

        float s = 0.f;
        #pragma unroll
        for (int i = 0; i < 10; i++) { l[i] = __expf(l[i] - bestL); s += l[i]; }
        #pragma unroll
        for (int off = 16; off; off >>= 1) s += __shfl_xor_sync(0xffffffffu, s, off);
        float inv = 1.0f / s;
        #pragma unroll
        for (int i = 0; i < 5; i++) {
            int v0 = (lane + i * 32) * 2;
            sAvg[wid][v0]     += l[2*i]   * inv;
            sAvg[wid][v0 + 1] += l[2*i+1] * inv;
        }

        // argmax table entry: [(t,g), b]
        if (lane == 0)
            g_k1[((n & (NT - 1)) * NG + g) * NB + (n >> 10)] = (unsigned short)k1;

        float4 cb = ((const float4*)(codebook + (size_t)(g * NV + k2) * ND))[lane];
        ((float4*)(out + (size_t)n * (NG * ND) + g * ND))[lane] = cb;

        __syncwarp();
        if (it + 2 < 4) prefetch(slot, task + 16);
    }

    __syncthreads();
    for (int xx = tid; xx < NG * NV; xx += 256) {
        int gg = xx / NV, v = xx - gg * NV;
        float s = sAvg[gg][v] + sAvg[gg + 2][v] + sAvg[gg + 4][v] + sAvg[gg + 6][v];
        atomicAdd(&g_avg[xx], s);
    }
}

// ---------------- perplexity: match-based code rows + float4 avg rows ----------------
__global__ __launch_bounds__(256) void perp_kernel(float* __restrict__ out) {
    const int row = blockIdx.x * 8 + (threadIdx.x >> 5);
    const int lane = threadIdx.x & 31;
    if (row < NT * NG) {
        // 16 argmax indices -> exact count entropy via match.any
        unsigned key = (lane < NB) ? (unsigned)g_k1[row * NB + lane]
                                   : 0x10000u + (unsigned)lane;   // unique sentinel
        unsigned mask = __match_any_sync(0xffffffffu, key);
        float t = 0.f;
        if (lane < NB && lane == (__ffs(mask) - 1)) {
            float p = (float)__popc(mask) * (1.0f / NB);
            t = p * __logf(p + 1e-7f);
        }
        #pragma unroll
        for (int off = 16; off; off >>= 1) t += __shfl_xor_sync(0xffffffffu, t, off);
        if (lane == 0) atomicAdd(out + 0, __expf(-t));
    } else if (row < NT * NG + NG) {
        const float4* v4 = (const float4*)(g_avg + (size_t)(row - NT * NG) * NV);
        const float scale = 1.0f / (float)NTOK;
        float t = 0.f;
        #pragma unroll
        for (int i = 0; i < 2; i++) {
            float4 q = v4[lane + i * 32];
            float p0 = q.x * scale, p1 = q.y * scale, p2 = q.z * scale, p3 = q.w * scale;
            t += p0 * __logf(p0 + 1e-7f) + p1 * __logf(p1 + 1e-7f)
               + p2 * __logf(p2 + 1e-7f) + p3 * __logf(p3 + 1e-7f);
        }
        if (lane < 16) {
            float4 q = v4[lane + 64];
            float p0 = q.x * scale, p1 = q.y * scale, p2 = q.z * scale, p3 = q.w * scale;
            t += p0 * __logf(p0 + 1e-7f) + p1 * __logf(p1 + 1e-7f)
               + p2 * __logf(p2 + 1e-7f) + p3 * __logf(p3 + 1e-7f);
        }
        #pragma unroll
        for (int off = 16; off; off >>= 1) t += __shfl_xor_sync(0xffffffffu, t, off);
        if (lane == 0) atomicAdd(out + 1, __expf(-t));
    }
}

// ---------------- launch ----------------
extern "C" void kernel_launch(void* const* d_in, const int* in_sizes, int n_in,
                              void* d_out, int out_size)
{
    const float* x        = (const float*)d_in[0];  // (16,1024,512)
    const float* w_proj   = (const float*)d_in[1];  // (640,512)
    const float* b_proj   = (const float*)d_in[2];  // (640)
    const float* codebook = (const float*)d_in[3];  // (1,640,128)
    const float* gumbel   = (const float*)d_in[4];  // (16384,2,320)
    float* out = (float*)d_out;
    float* scalars = out + (out_size - 2);

    cudaFuncSetAttribute(gemm_mma_kernel, cudaFuncAttributeMaxDynamicSharedMemorySize, GEMM_SMEM);

    split_zero_kernel<<<(X4 + W4 + 1023) / 1024, 256>>>(
        (const float4*)x, (const float4*)w_proj, scalars);

    dim3 ggrid(NJ / 64, NTOK / 128);   // (10, 128) = 1280 CTAs
    gemm_mma_kernel<<<ggrid, 128, GEMM_SMEM>>>(b_proj);

    epilogue_kernel<<<1024, 256>>>(x, w_proj, b_proj, gumbel, codebook, out);

    perp_kernel<<<(NT * NG + NG + 7) / 8, 256>>>(scalars);
}